// round 10
// baseline (speedup 1.0000x reference)
#include <cuda_runtime.h>
#include <cuda_fp16.h>
#include <cstdint>
#include <math.h>

// ----------------------------------------------------------------------------
// Problem constants
// ----------------------------------------------------------------------------
#define Bn   4
#define Sn   2048
#define Dn   1024
#define Hn   16
#define HDn  64
#define Mrows (Bn*Sn)          // 8192
#define D4   (4*Dn)            // 4096

// ----------------------------------------------------------------------------
// Scratch (device globals -- no allocations allowed)
// ----------------------------------------------------------------------------
__device__ __half g_qkv  [(size_t)Mrows * 3 * Dn];
__device__ __half g_hA   [(size_t)Mrows * Dn];
__device__ __half g_at   [(size_t)Mrows * Dn];
__device__ __half g_h1   [(size_t)Mrows * D4];
__device__ __half g_wqkvT[(size_t)3 * Dn * Dn];
__device__ __half g_woT  [(size_t)Dn * Dn];
__device__ __half g_w1T  [(size_t)D4 * Dn];
__device__ __half g_w2T  [(size_t)Dn * D4];
__device__ float  g_bp[3 * Dn];

__device__ __forceinline__ uint32_t smem_u32(const void* p) {
    uint32_t a;
    asm("{ .reg .u64 t; cvta.to.shared.u64 t, %1; cvt.u32.u64 %0, t; }" : "=r"(a) : "l"(p));
    return a;
}
__device__ __forceinline__ void cp_async16(void* dst, const void* src) {
    asm volatile("cp.async.cg.shared.global [%0], [%1], 16;"
                 :: "r"(smem_u32(dst)), "l"(src) : "memory");
}
#define CP_COMMIT() asm volatile("cp.async.commit_group;" ::: "memory")
#define CP_WAIT(n)  asm volatile("cp.async.wait_group %0;" :: "n"(n) : "memory")

__device__ __forceinline__ void ldsm_x4(uint32_t* r, uint32_t a) {
    asm volatile("ldmatrix.sync.aligned.m8n8.x4.shared.b16 {%0,%1,%2,%3}, [%4];"
                 : "=r"(r[0]), "=r"(r[1]), "=r"(r[2]), "=r"(r[3]) : "r"(a));
}
__device__ __forceinline__ void ldsm_x4_t(uint32_t* r, uint32_t a) {
    asm volatile("ldmatrix.sync.aligned.m8n8.x4.trans.shared.b16 {%0,%1,%2,%3}, [%4];"
                 : "=r"(r[0]), "=r"(r[1]), "=r"(r[2]), "=r"(r[3]) : "r"(a));
}
__device__ __forceinline__ void mma16816(float* d, const uint32_t* a, const uint32_t* b) {
    asm volatile("mma.sync.aligned.m16n8k16.row.col.f32.f16.f16.f32 "
                 "{%0,%1,%2,%3}, {%4,%5,%6,%7}, {%8,%9}, {%0,%1,%2,%3};"
                 : "+f"(d[0]), "+f"(d[1]), "+f"(d[2]), "+f"(d[3])
                 : "r"(a[0]), "r"(a[1]), "r"(a[2]), "r"(a[3]), "r"(b[0]), "r"(b[1]));
}

// ----------------------------------------------------------------------------
// Fused QKV transpose+pack
// ----------------------------------------------------------------------------
__global__ void qkv_pack_kernel(const float* __restrict__ Wq,
                                const float* __restrict__ Wk,
                                const float* __restrict__ Wv,
                                __half* __restrict__ dst)
{
    __shared__ float t[32][33];
    int z = blockIdx.z;
    int w = z >> 4, zh = z & 15;
    const float* src = (w == 0 ? Wq : w == 1 ? Wk : Wv) + (size_t)zh * Dn * HDn;
    int n0 = blockIdx.x * 32, k0 = blockIdx.y * 32;
    int tx = threadIdx.x, ty = threadIdx.y;
    #pragma unroll
    for (int j = 0; j < 4; j++) {
        int k = k0 + ty + j * 8;
        t[ty + j * 8][tx] = src[(size_t)k * HDn + n0 + tx];
    }
    __syncthreads();
    int row_base = w * Dn + zh * HDn;
    #pragma unroll
    for (int j = 0; j < 4; j++) {
        int n = n0 + ty + j * 8;
        size_t o = (size_t)(row_base + n) * Dn + k0 + tx;
        dst[o] = __float2half_rn(t[tx][ty + j * 8]);
    }
}

__global__ void transpose_pack_kernel(const float* __restrict__ src,
                                      __half* __restrict__ dst,
                                      int Ks, int Ns)
{
    __shared__ float t[32][33];
    int n0 = blockIdx.x * 32, k0 = blockIdx.y * 32;
    int tx = threadIdx.x, ty = threadIdx.y;
    #pragma unroll
    for (int j = 0; j < 4; j++) {
        int k = k0 + ty + j * 8;
        t[ty + j * 8][tx] = src[(size_t)k * Ns + n0 + tx];
    }
    __syncthreads();
    #pragma unroll
    for (int j = 0; j < 4; j++) {
        int n = n0 + ty + j * 8;
        size_t o = (size_t)n * Ks + k0 + tx;
        dst[o] = __float2half_rn(t[tx][ty + j * 8]);
    }
}

__global__ void bias_pack_kernel(const float* __restrict__ bq,
                                 const float* __restrict__ bk,
                                 const float* __restrict__ bv,
                                 float* __restrict__ bp)
{
    int idx = blockIdx.x * 256 + threadIdx.x;
    if (idx < 3 * Dn) {
        int w = idx >> 10, c = idx & 1023;
        bp[idx] = (w == 0 ? bq : w == 1 ? bk : bv)[c];
    }
}

// ----------------------------------------------------------------------------
// LayerNorm -> fp16.
// ----------------------------------------------------------------------------
__global__ void __launch_bounds__(256) ln_kernel(const float* __restrict__ X,
                                                 const float* __restrict__ gamma,
                                                 const float* __restrict__ beta,
                                                 __half* __restrict__ Y)
{
    int row = blockIdx.x;
    int tid = threadIdx.x;
    float4 xv = ((const float4*)(X + (size_t)row * Dn))[tid];

    __shared__ float red[8];
    float s = xv.x + xv.y + xv.z + xv.w;
    #pragma unroll
    for (int o = 16; o > 0; o >>= 1) s += __shfl_xor_sync(0xffffffffu, s, o);
    if ((tid & 31) == 0) red[tid >> 5] = s;
    __syncthreads();
    float mu = (red[0]+red[1]+red[2]+red[3]+red[4]+red[5]+red[6]+red[7]) * (1.0f / Dn);
    __syncthreads();

    float dx = xv.x - mu, dy = xv.y - mu, dz = xv.z - mu, dw = xv.w - mu;
    float sq = dx*dx + dy*dy + dz*dz + dw*dw;
    #pragma unroll
    for (int o = 16; o > 0; o >>= 1) sq += __shfl_xor_sync(0xffffffffu, sq, o);
    if ((tid & 31) == 0) red[tid >> 5] = sq;
    __syncthreads();
    float var = (red[0]+red[1]+red[2]+red[3]+red[4]+red[5]+red[6]+red[7]) * (1.0f / Dn);
    float inv = rsqrtf(var + 1e-5f);

    float4 gv = ((const float4*)gamma)[tid];
    float4 bv = ((const float4*)beta)[tid];
    float o0 = dx*inv*gv.x + bv.x, o1 = dy*inv*gv.y + bv.y;
    float o2 = dz*inv*gv.z + bv.z, o3 = dw*inv*gv.w + bv.w;

    size_t off = (size_t)row * Dn + tid * 4;
    *(__half2*)&Y[off]     = __floats2half2_rn(o0, o1);
    *(__half2*)&Y[off + 2] = __floats2half2_rn(o2, o3);
}

// ----------------------------------------------------------------------------
// Raw mma.sync fp16 GEMM: block tile 128x256, warp tile 64x64, BK=64,
// 3-stage cp.async, 8 warps. MMA:LDSM = 32:8 per k16 slice per warp.
// ----------------------------------------------------------------------------
__device__ __forceinline__ float gelu_exact(float v) {
    return 0.5f * v * (1.0f + erff(v * 0.70710678118654752f));
}

#define BK     64
#define KPITCH 72
#define ATILEB (128 * KPITCH * 2)        // 18432 B
#define BTILEB (256 * KPITCH * 2)        // 36864 B
#define STAGEB (ATILEB + BTILEB)         // 55296 B
#define NSTAGE 3
#define GEMM_SMEM (NSTAGE * STAGEB)      // 165888 B
#define SPITCH 260                       // fp32 staging pitch (133120 B)

template <bool GELU_, bool RES_, bool OUTF, bool OUTB>
__global__ void __launch_bounds__(256) mma_gemm_kernel(
    const __half* __restrict__ A, const __half* __restrict__ B,
    const float* __restrict__ bias, const float* __restrict__ residual,
    float* __restrict__ Cf, __half* __restrict__ Ch,
    int N, int K)
{
    extern __shared__ __align__(128) char smem[];
    float* stg = (float*)smem;

    const int tid = threadIdx.x;
    const int wid = tid >> 5;
    const int lane = tid & 31;
    const int wm = wid >> 2;          // 0..1  (64-row band)
    const int wn = wid & 3;           // 0..3  (64-col band)
    const int bx = blockIdx.x, by = blockIdx.y;

    const size_t arow = (size_t)by * 128;
    const size_t brow = (size_t)bx * 256;

    auto load_chunk = [&](int kc, int st) {
        char* base = smem + st * STAGEB;
        __half* A_s = (__half*)(base);
        __half* B_s = (__half*)(base + ATILEB);
        #pragma unroll
        for (int i = 0; i < 4; i++) {             // A: 1024 f4
            int idx = tid + i * 256;
            int row = idx >> 3, c = idx & 7;
            cp_async16(&A_s[row * KPITCH + c * 8],
                       A + (arow + row) * (size_t)K + kc * BK + c * 8);
        }
        #pragma unroll
        for (int i = 0; i < 8; i++) {             // B: 2048 f4
            int idx = tid + i * 256;
            int row = idx >> 3, c = idx & 7;
            cp_async16(&B_s[row * KPITCH + c * 8],
                       B + (brow + row) * (size_t)K + kc * BK + c * 8);
        }
    };

    float acc[4][8][4];
    #pragma unroll
    for (int i = 0; i < 4; i++)
        #pragma unroll
        for (int n = 0; n < 8; n++)
            #pragma unroll
            for (int e = 0; e < 4; e++) acc[i][n][e] = 0.0f;

    const int a_r  = wm * 64 + (lane & 15);
    const int a_k  = (lane >> 4) << 3;
    const int b_r  = wn * 64 + ((lane >> 4) << 3) + (lane & 7);
    const int b_k  = ((lane >> 3) & 1) << 3;

    const int nk = K / BK;
    load_chunk(0, 0); CP_COMMIT();
    load_chunk(1, 1); CP_COMMIT();

    for (int kc = 0; kc < nk; kc++) {
        const int st = kc % NSTAGE;
        if (kc + 2 < nk) { load_chunk(kc + 2, (kc + 2) % NSTAGE); CP_COMMIT(); }
        if      (kc + 2 < nk) CP_WAIT(2);
        else if (kc + 1 < nk) CP_WAIT(1);
        else                  CP_WAIT(0);
        __syncthreads();

        char* base = smem + st * STAGEB;
        const uint32_t uA = smem_u32(base);
        const uint32_t uB = smem_u32(base + ATILEB);

        #pragma unroll
        for (int ks = 0; ks < BK / 16; ks++) {
            uint32_t a[4][4], b[4][4];
            const int kof = ks * 16;
            #pragma unroll
            for (int i = 0; i < 4; i++)
                ldsm_x4(a[i], uA + (uint32_t)(((a_r + i * 16) * KPITCH + kof + a_k) * 2));
            #pragma unroll
            for (int g = 0; g < 4; g++)
                ldsm_x4(b[g], uB + (uint32_t)(((b_r + g * 16) * KPITCH + kof + b_k) * 2));
            #pragma unroll
            for (int i = 0; i < 4; i++)
                #pragma unroll
                for (int n = 0; n < 8; n++)
                    mma16816(acc[i][n], a[i], &b[n >> 1][(n & 1) * 2]);
        }
        __syncthreads();
    }

    // Stage accumulators to smem, fused epilogue to GMEM.
    const int c_r = lane >> 2;
    const int c_c = (lane & 3) << 1;
    #pragma unroll
    for (int i = 0; i < 4; i++)
        #pragma unroll
        for (int n = 0; n < 8; n++) {
            int r0 = wm * 64 + i * 16 + c_r;
            int c0 = wn * 64 + n * 8 + c_c;
            stg[r0 * SPITCH + c0]           = acc[i][n][0];
            stg[r0 * SPITCH + c0 + 1]       = acc[i][n][1];
            stg[(r0 + 8) * SPITCH + c0]     = acc[i][n][2];
            stg[(r0 + 8) * SPITCH + c0 + 1] = acc[i][n][3];
        }
    __syncthreads();

    const int cc = tid & 63;                   // 64 f4-columns
    const int rg = tid >> 6;                   // 4 row groups of 32
    const int ncol = bx * 256 + cc * 4;
    float4 bb = *(const float4*)&bias[ncol];
    #pragma unroll 4
    for (int rr = 0; rr < 32; rr++) {
        int row = rg * 32 + rr;
        size_t m = arow + row;
        float4 v = *(float4*)&stg[row * SPITCH + cc * 4];
        v.x += bb.x; v.y += bb.y; v.z += bb.z; v.w += bb.w;
        if (GELU_) {
            v.x = gelu_exact(v.x); v.y = gelu_exact(v.y);
            v.z = gelu_exact(v.z); v.w = gelu_exact(v.w);
        }
        if (RES_) {
            float4 rv = *(const float4*)&residual[m * N + ncol];
            v.x += rv.x; v.y += rv.y; v.z += rv.z; v.w += rv.w;
        }
        if (OUTF) *(float4*)&Cf[m * N + ncol] = v;
        if (OUTB) {
            size_t o = m * N + ncol;
            *(__half2*)&Ch[o]     = __floats2half2_rn(v.x, v.y);
            *(__half2*)&Ch[o + 2] = __floats2half2_rn(v.z, v.w);
        }
    }
}

// ----------------------------------------------------------------------------
// Tensor-core flash attention (validated R9). 128 threads, 64-query tile.
// ----------------------------------------------------------------------------
#define AQP 72
#define ATT_SMEM (5 * 64 * AQP * 2)

__global__ void __launch_bounds__(128) attn_mma_kernel(const __half* __restrict__ QKV,
                                                       __half* __restrict__ O)
{
    extern __shared__ __align__(16) __half smh[];
    __half* Qs = smh;

    int qb = blockIdx.x;
    int bh = blockIdx.y;
    int b = bh >> 4, h = bh & 15;
    int tid = threadIdx.x, w = tid >> 5, lane = tid & 31;

    const size_t rowbase = (size_t)(b * Sn) * 3072 + (size_t)h * 64;

    #pragma unroll
    for (int i = 0; i < 4; i++) {
        int idx = tid + i * 128;
        int row = idx >> 3, c = idx & 7;
        cp_async16(&Qs[row * AQP + c * 8],
                   QKV + rowbase + (size_t)(qb * 64 + row) * 3072 + c * 8);
    }
    CP_COMMIT();

    auto load_kv = [&](int kb, int st) {
        __half* K_s = smh + 64 * AQP * (1 + st);
        __half* V_s = smh + 64 * AQP * (3 + st);
        #pragma unroll
        for (int i = 0; i < 4; i++) {
            int idx = tid + i * 128;
            int row = idx >> 3, c = idx & 7;
            size_t src = rowbase + (size_t)(kb * 64 + row) * 3072 + c * 8;
            cp_async16(&K_s[row * AQP + c * 8], QKV + src + 1024);
            cp_async16(&V_s[row * AQP + c * 8], QKV + src + 2048);
        }
    };
    load_kv(0, 0); CP_COMMIT();
    CP_WAIT(0);
    __syncthreads();

    uint32_t aQ[4][4];
    {
        const uint32_t uQ = smem_u32(Qs);
        int a_r = w * 16 + (lane & 15);
        int a_k = (lane >> 4) << 3;
        #pragma unroll
        for (int t = 0; t < 4; t++)
            ldsm_x4(aQ[t], uQ + (uint32_t)((a_r * AQP + t * 16 + a_k) * 2));
    }

    const int bk_r = ((lane >> 4) << 3) + (lane & 7);
    const int bk_k = ((lane >> 3) & 1) << 3;
    const int bv_r = (((lane >> 3) & 1) << 3) + (lane & 7);
    const int bv_c = (lane >> 4) << 3;

    float o[8][4];
    #pragma unroll
    for (int j = 0; j < 8; j++)
        #pragma unroll
        for (int e = 0; e < 4; e++) o[j][e] = 0.0f;
    float m0 = -1e30f, m1 = -1e30f, l0 = 0.0f, l1 = 0.0f;

    const int qg0 = qb * 64 + w * 16 + (lane >> 2);

    for (int kb = 0; kb <= qb; kb++) {
        const int st = kb & 1;
        if (kb < qb) { load_kv(kb + 1, st ^ 1); CP_COMMIT(); }

        const uint32_t uK = smem_u32(smh + 64 * AQP * (1 + st));
        const uint32_t uV = smem_u32(smh + 64 * AQP * (3 + st));

        float s[8][4];
        #pragma unroll
        for (int j = 0; j < 8; j++)
            #pragma unroll
            for (int e = 0; e < 4; e++) s[j][e] = 0.0f;
        #pragma unroll
        for (int t = 0; t < 4; t++) {
            uint32_t bK[4][4];
            #pragma unroll
            for (int g = 0; g < 4; g++)
                ldsm_x4(bK[g], uK + (uint32_t)(((g * 16 + bk_r) * AQP + t * 16 + bk_k) * 2));
            #pragma unroll
            for (int j = 0; j < 8; j++)
                mma16816(s[j], aQ[t], &bK[j >> 1][(j & 1) * 2]);
        }

        #pragma unroll
        for (int j = 0; j < 8; j++)
            #pragma unroll
            for (int e = 0; e < 4; e++) s[j][e] *= 0.125f;
        if (kb == qb) {
            #pragma unroll
            for (int j = 0; j < 8; j++) {
                int col = kb * 64 + j * 8 + (lane & 3) * 2;
                if (col     > qg0)     s[j][0] = -1e30f;
                if (col + 1 > qg0)     s[j][1] = -1e30f;
                if (col     > qg0 + 8) s[j][2] = -1e30f;
                if (col + 1 > qg0 + 8) s[j][3] = -1e30f;
            }
        }

        float ml0 = -1e30f, ml1 = -1e30f;
        #pragma unroll
        for (int j = 0; j < 8; j++) {
            ml0 = fmaxf(ml0, fmaxf(s[j][0], s[j][1]));
            ml1 = fmaxf(ml1, fmaxf(s[j][2], s[j][3]));
        }
        ml0 = fmaxf(ml0, __shfl_xor_sync(0xffffffffu, ml0, 1));
        ml0 = fmaxf(ml0, __shfl_xor_sync(0xffffffffu, ml0, 2));
        ml1 = fmaxf(ml1, __shfl_xor_sync(0xffffffffu, ml1, 1));
        ml1 = fmaxf(ml1, __shfl_xor_sync(0xffffffffu, ml1, 2));

        float mn0 = fmaxf(m0, ml0), mn1 = fmaxf(m1, ml1);
        float al0 = __expf(m0 - mn0), al1 = __expf(m1 - mn1);

        float ls0 = 0.0f, ls1 = 0.0f;
        uint32_t pfrag[4][4];
        #pragma unroll
        for (int j = 0; j < 8; j++) {
            float p0 = __expf(s[j][0] - mn0);
            float p1 = __expf(s[j][1] - mn0);
            float p2 = __expf(s[j][2] - mn1);
            float p3 = __expf(s[j][3] - mn1);
            ls0 += p0 + p1; ls1 += p2 + p3;
            int t = j >> 1, hi = (j & 1) * 2;
            __half2 h01 = __floats2half2_rn(p0, p1);
            __half2 h23 = __floats2half2_rn(p2, p3);
            pfrag[t][hi]     = *(uint32_t*)&h01;
            pfrag[t][hi + 1] = *(uint32_t*)&h23;
        }
        ls0 += __shfl_xor_sync(0xffffffffu, ls0, 1);
        ls0 += __shfl_xor_sync(0xffffffffu, ls0, 2);
        ls1 += __shfl_xor_sync(0xffffffffu, ls1, 1);
        ls1 += __shfl_xor_sync(0xffffffffu, ls1, 2);

        l0 = l0 * al0 + ls0;  l1 = l1 * al1 + ls1;
        m0 = mn0;             m1 = mn1;
        #pragma unroll
        for (int j = 0; j < 8; j++) {
            o[j][0] *= al0; o[j][1] *= al0;
            o[j][2] *= al1; o[j][3] *= al1;
        }

        #pragma unroll
        for (int t = 0; t < 4; t++) {
            uint32_t bV[4][4];
            #pragma unroll
            for (int g = 0; g < 4; g++)
                ldsm_x4_t(bV[g], uV + (uint32_t)(((t * 16 + bv_r) * AQP + g * 16 + bv_c) * 2));
            #pragma unroll
            for (int j = 0; j < 8; j++)
                mma16816(o[j], pfrag[t], &bV[j >> 1][(j & 1) * 2]);
        }

        if (kb < qb) CP_WAIT(0);
        __syncthreads();
    }

    float inv0 = 1.0f / l0, inv1 = 1.0f / l1;
    size_t ob = (size_t)(b * Sn + qb * 64 + w * 16 + (lane >> 2)) * Dn + h * 64;
    #pragma unroll
    for (int j = 0; j < 8; j++) {
        int col = j * 8 + (lane & 3) * 2;
        __half2 v0 = __floats2half2_rn(o[j][0] * inv0, o[j][1] * inv0);
        __half2 v1 = __floats2half2_rn(o[j][2] * inv1, o[j][3] * inv1);
        *(__half2*)&O[ob + col]           = v0;
        *(__half2*)&O[ob + 8 * Dn + col]  = v1;
    }
}

// ----------------------------------------------------------------------------
// Launch (launch 3 = QKV GEMM for ncu capture)
// ----------------------------------------------------------------------------
extern "C" void kernel_launch(void* const* d_in, const int* in_sizes, int n_in,
                              void* d_out, int out_size)
{
    const float* x     = (const float*)d_in[0];
    const float* Wq    = (const float*)d_in[1];
    const float* Wk    = (const float*)d_in[2];
    const float* Wv    = (const float*)d_in[3];
    const float* bq    = (const float*)d_in[4];
    const float* bk    = (const float*)d_in[5];
    const float* bv    = (const float*)d_in[6];
    const float* Wo    = (const float*)d_in[7];
    const float* bo    = (const float*)d_in[8];
    const float* W1    = (const float*)d_in[9];
    const float* b1    = (const float*)d_in[10];
    const float* W2    = (const float*)d_in[11];
    const float* b2    = (const float*)d_in[12];
    const float* gamma = (const float*)d_in[13];
    const float* beta  = (const float*)d_in[14];
    float* out = (float*)d_out;

    float *bp;
    __half *qkv, *hA, *at, *h1, *wq, *wo, *w1, *w2;
    cudaGetSymbolAddress((void**)&qkv, g_qkv);
    cudaGetSymbolAddress((void**)&bp,  g_bp);
    cudaGetSymbolAddress((void**)&hA,  g_hA);
    cudaGetSymbolAddress((void**)&at,  g_at);
    cudaGetSymbolAddress((void**)&h1,  g_h1);
    cudaGetSymbolAddress((void**)&wq,  g_wqkvT);
    cudaGetSymbolAddress((void**)&wo,  g_woT);
    cudaGetSymbolAddress((void**)&w1,  g_w1T);
    cudaGetSymbolAddress((void**)&w2,  g_w2T);

    cudaFuncSetAttribute(mma_gemm_kernel<false, false, false, true >,
                         cudaFuncAttributeMaxDynamicSharedMemorySize, GEMM_SMEM);
    cudaFuncSetAttribute(mma_gemm_kernel<false, true,  true,  false>,
                         cudaFuncAttributeMaxDynamicSharedMemorySize, GEMM_SMEM);
    cudaFuncSetAttribute(mma_gemm_kernel<true,  false, false, true >,
                         cudaFuncAttributeMaxDynamicSharedMemorySize, GEMM_SMEM);
    cudaFuncSetAttribute(attn_mma_kernel,
                         cudaFuncAttributeMaxDynamicSharedMemorySize, ATT_SMEM);

    dim3 tb(32, 8);
    qkv_pack_kernel<<<dim3(2, 32, 48), tb>>>(Wq, Wk, Wv, wq);
    bias_pack_kernel<<<12, 256>>>(bq, bk, bv, bp);
    ln_kernel<<<Mrows, 256>>>(x, gamma, beta, hA);

    // 3: QKV GEMM -> fp16 qkv   (ncu capture lands here)
    mma_gemm_kernel<false, false, false, true><<<dim3(3 * Dn / 256, Mrows / 128), 256, GEMM_SMEM>>>(
        hA, wq, bp, x, out, qkv, 3 * Dn, Dn);

    // 4: tensor-core attention -> fp16 at
    attn_mma_kernel<<<dim3(Sn / 64, Bn * Hn), 128, ATT_SMEM>>>(qkv, at);

    // Wo pack + GEMM (+x residual) -> fp32 out
    transpose_pack_kernel<<<dim3(32, 32), tb>>>(Wo, wo, Dn, Dn);
    mma_gemm_kernel<false, true, true, false><<<dim3(Dn / 256, Mrows / 128), 256, GEMM_SMEM>>>(
        at, wo, bo, x, out, qkv, Dn, Dn);

    // LN2
    ln_kernel<<<Mrows, 256>>>(out, gamma, beta, hA);

    // W1 pack + MLP1 (+GELU) -> fp16 h1
    transpose_pack_kernel<<<dim3(128, 32), tb>>>(W1, w1, Dn, D4);
    mma_gemm_kernel<true, false, false, true><<<dim3(D4 / 256, Mrows / 128), 256, GEMM_SMEM>>>(
        hA, w1, b1, x, out, h1, D4, Dn);

    // W2 pack + MLP2 (+out residual) -> fp32 out
    transpose_pack_kernel<<<dim3(32, 128), tb>>>(W2, w2, D4, Dn);
    mma_gemm_kernel<false, true, true, false><<<dim3(Dn / 256, Mrows / 128), 256, GEMM_SMEM>>>(
        h1, w2, b2, out, out, qkv, Dn, D4);
}

// round 11
// speedup vs baseline: 1.0944x; 1.0944x over previous
#include <cuda_runtime.h>
#include <cuda_fp16.h>
#include <cstdint>
#include <math.h>

// ----------------------------------------------------------------------------
// Problem constants
// ----------------------------------------------------------------------------
#define Bn   4
#define Sn   2048
#define Dn   1024
#define Hn   16
#define HDn  64
#define Mrows (Bn*Sn)          // 8192
#define D4   (4*Dn)            // 4096

// ----------------------------------------------------------------------------
// Scratch (device globals -- no allocations allowed)
// ----------------------------------------------------------------------------
__device__ __half g_qkv  [(size_t)Mrows * 3 * Dn];
__device__ __half g_hA   [(size_t)Mrows * Dn];
__device__ __half g_at   [(size_t)Mrows * Dn];
__device__ __half g_h1   [(size_t)Mrows * D4];
__device__ __half g_wqkvT[(size_t)3 * Dn * Dn];
__device__ __half g_woT  [(size_t)Dn * Dn];
__device__ __half g_w1T  [(size_t)D4 * Dn];
__device__ __half g_w2T  [(size_t)Dn * D4];
__device__ float  g_bp[3 * Dn];

__device__ __forceinline__ uint32_t smem_u32(const void* p) {
    uint32_t a;
    asm("{ .reg .u64 t; cvta.to.shared.u64 t, %1; cvt.u32.u64 %0, t; }" : "=r"(a) : "l"(p));
    return a;
}
__device__ __forceinline__ void cp_async16(void* dst, const void* src) {
    asm volatile("cp.async.cg.shared.global [%0], [%1], 16;"
                 :: "r"(smem_u32(dst)), "l"(src) : "memory");
}
#define CP_COMMIT() asm volatile("cp.async.commit_group;" ::: "memory")
#define CP_WAIT(n)  asm volatile("cp.async.wait_group %0;" :: "n"(n) : "memory")

__device__ __forceinline__ void ldsm_x4(uint32_t* r, uint32_t a) {
    asm volatile("ldmatrix.sync.aligned.m8n8.x4.shared.b16 {%0,%1,%2,%3}, [%4];"
                 : "=r"(r[0]), "=r"(r[1]), "=r"(r[2]), "=r"(r[3]) : "r"(a));
}
__device__ __forceinline__ void ldsm_x4_t(uint32_t* r, uint32_t a) {
    asm volatile("ldmatrix.sync.aligned.m8n8.x4.trans.shared.b16 {%0,%1,%2,%3}, [%4];"
                 : "=r"(r[0]), "=r"(r[1]), "=r"(r[2]), "=r"(r[3]) : "r"(a));
}
__device__ __forceinline__ void mma16816(float* d, const uint32_t* a, const uint32_t* b) {
    asm volatile("mma.sync.aligned.m16n8k16.row.col.f32.f16.f16.f32 "
                 "{%0,%1,%2,%3}, {%4,%5,%6,%7}, {%8,%9}, {%0,%1,%2,%3};"
                 : "+f"(d[0]), "+f"(d[1]), "+f"(d[2]), "+f"(d[3])
                 : "r"(a[0]), "r"(a[1]), "r"(a[2]), "r"(a[3]), "r"(b[0]), "r"(b[1]));
}

// ----------------------------------------------------------------------------
// Fused QKV transpose+pack
// ----------------------------------------------------------------------------
__global__ void qkv_pack_kernel(const float* __restrict__ Wq,
                                const float* __restrict__ Wk,
                                const float* __restrict__ Wv,
                                __half* __restrict__ dst)
{
    __shared__ float t[32][33];
    int z = blockIdx.z;
    int w = z >> 4, zh = z & 15;
    const float* src = (w == 0 ? Wq : w == 1 ? Wk : Wv) + (size_t)zh * Dn * HDn;
    int n0 = blockIdx.x * 32, k0 = blockIdx.y * 32;
    int tx = threadIdx.x, ty = threadIdx.y;
    #pragma unroll
    for (int j = 0; j < 4; j++) {
        int k = k0 + ty + j * 8;
        t[ty + j * 8][tx] = src[(size_t)k * HDn + n0 + tx];
    }
    __syncthreads();
    int row_base = w * Dn + zh * HDn;
    #pragma unroll
    for (int j = 0; j < 4; j++) {
        int n = n0 + ty + j * 8;
        size_t o = (size_t)(row_base + n) * Dn + k0 + tx;
        dst[o] = __float2half_rn(t[tx][ty + j * 8]);
    }
}

__global__ void transpose_pack_kernel(const float* __restrict__ src,
                                      __half* __restrict__ dst,
                                      int Ks, int Ns)
{
    __shared__ float t[32][33];
    int n0 = blockIdx.x * 32, k0 = blockIdx.y * 32;
    int tx = threadIdx.x, ty = threadIdx.y;
    #pragma unroll
    for (int j = 0; j < 4; j++) {
        int k = k0 + ty + j * 8;
        t[ty + j * 8][tx] = src[(size_t)k * Ns + n0 + tx];
    }
    __syncthreads();
    #pragma unroll
    for (int j = 0; j < 4; j++) {
        int n = n0 + ty + j * 8;
        size_t o = (size_t)n * Ks + k0 + tx;
        dst[o] = __float2half_rn(t[tx][ty + j * 8]);
    }
}

__global__ void bias_pack_kernel(const float* __restrict__ bq,
                                 const float* __restrict__ bk,
                                 const float* __restrict__ bv,
                                 float* __restrict__ bp)
{
    int idx = blockIdx.x * 256 + threadIdx.x;
    if (idx < 3 * Dn) {
        int w = idx >> 10, c = idx & 1023;
        bp[idx] = (w == 0 ? bq : w == 1 ? bk : bv)[c];
    }
}

// ----------------------------------------------------------------------------
// LayerNorm -> fp16.
// ----------------------------------------------------------------------------
__global__ void __launch_bounds__(256) ln_kernel(const float* __restrict__ X,
                                                 const float* __restrict__ gamma,
                                                 const float* __restrict__ beta,
                                                 __half* __restrict__ Y)
{
    int row = blockIdx.x;
    int tid = threadIdx.x;
    float4 xv = ((const float4*)(X + (size_t)row * Dn))[tid];

    __shared__ float red[8];
    float s = xv.x + xv.y + xv.z + xv.w;
    #pragma unroll
    for (int o = 16; o > 0; o >>= 1) s += __shfl_xor_sync(0xffffffffu, s, o);
    if ((tid & 31) == 0) red[tid >> 5] = s;
    __syncthreads();
    float mu = (red[0]+red[1]+red[2]+red[3]+red[4]+red[5]+red[6]+red[7]) * (1.0f / Dn);
    __syncthreads();

    float dx = xv.x - mu, dy = xv.y - mu, dz = xv.z - mu, dw = xv.w - mu;
    float sq = dx*dx + dy*dy + dz*dz + dw*dw;
    #pragma unroll
    for (int o = 16; o > 0; o >>= 1) sq += __shfl_xor_sync(0xffffffffu, sq, o);
    if ((tid & 31) == 0) red[tid >> 5] = sq;
    __syncthreads();
    float var = (red[0]+red[1]+red[2]+red[3]+red[4]+red[5]+red[6]+red[7]) * (1.0f / Dn);
    float inv = rsqrtf(var + 1e-5f);

    float4 gv = ((const float4*)gamma)[tid];
    float4 bv = ((const float4*)beta)[tid];
    float o0 = dx*inv*gv.x + bv.x, o1 = dy*inv*gv.y + bv.y;
    float o2 = dz*inv*gv.z + bv.z, o3 = dw*inv*gv.w + bv.w;

    size_t off = (size_t)row * Dn + tid * 4;
    *(__half2*)&Y[off]     = __floats2half2_rn(o0, o1);
    *(__half2*)&Y[off + 2] = __floats2half2_rn(o2, o3);
}

// ----------------------------------------------------------------------------
// Raw mma.sync fp16 GEMM: block tile 128x128, 4 warps (warp tile 64x64),
// BK=64, 2-stage cp.async, one __syncthreads per chunk, 3 CTAs/SM.
// MMA:LDSM = 32:8 per k16 slice per warp.
// ----------------------------------------------------------------------------
__device__ __forceinline__ float gelu_exact(float v) {
    return 0.5f * v * (1.0f + erff(v * 0.70710678118654752f));
}

#define BK     64
#define KPITCH 72
#define TILEB  (128 * KPITCH * 2)        // 18432 B
#define STAGEB (2 * TILEB)               // 36864 B (A + B)
#define NSTAGE 2
#define GEMM_SMEM (NSTAGE * STAGEB)      // 73728 B -> 3 CTAs/SM
#define SPITCH 132                       // fp32 staging pitch (67584 B, fits)

template <bool GELU_, bool RES_, bool OUTF, bool OUTB>
__global__ void __launch_bounds__(128, 3) mma_gemm_kernel(
    const __half* __restrict__ A, const __half* __restrict__ B,
    const float* __restrict__ bias, const float* __restrict__ residual,
    float* __restrict__ Cf, __half* __restrict__ Ch,
    int N, int K)
{
    extern __shared__ __align__(128) char smem[];
    float* stg = (float*)smem;

    const int tid = threadIdx.x;
    const int wid = tid >> 5;
    const int lane = tid & 31;
    const int wm = wid >> 1;          // 0..1  (64-row band)
    const int wn = wid & 1;           // 0..1  (64-col band)
    const int bx = blockIdx.x, by = blockIdx.y;

    const size_t arow = (size_t)by * 128;
    const size_t brow = (size_t)bx * 128;

    auto load_chunk = [&](int kc, int st) {
        char* base = smem + st * STAGEB;
        __half* A_s = (__half*)(base);
        __half* B_s = (__half*)(base + TILEB);
        #pragma unroll
        for (int i = 0; i < 8; i++) {            // 1024 f4 each, 128 thr
            int idx = tid + i * 128;
            int row = idx >> 3, c = idx & 7;
            int so = row * KPITCH + c * 8;
            cp_async16(&A_s[so], A + (arow + row) * (size_t)K + kc * BK + c * 8);
            cp_async16(&B_s[so], B + (brow + row) * (size_t)K + kc * BK + c * 8);
        }
    };

    float acc[4][8][4];
    #pragma unroll
    for (int i = 0; i < 4; i++)
        #pragma unroll
        for (int n = 0; n < 8; n++)
            #pragma unroll
            for (int e = 0; e < 4; e++) acc[i][n][e] = 0.0f;

    const int a_r  = wm * 64 + (lane & 15);
    const int a_k  = (lane >> 4) << 3;
    const int b_r  = wn * 64 + ((lane >> 4) << 3) + (lane & 7);
    const int b_k  = ((lane >> 3) & 1) << 3;

    const int nk = K / BK;
    load_chunk(0, 0); CP_COMMIT();

    for (int kc = 0; kc < nk; kc++) {
        const int st = kc & 1;
        CP_WAIT(0);
        __syncthreads();
        if (kc + 1 < nk) { load_chunk(kc + 1, st ^ 1); CP_COMMIT(); }

        char* base = smem + st * STAGEB;
        const uint32_t uA = smem_u32(base);
        const uint32_t uB = smem_u32(base + TILEB);

        #pragma unroll
        for (int ks = 0; ks < BK / 16; ks++) {
            const int kof = ks * 16;
            uint32_t a[4][4];
            #pragma unroll
            for (int i = 0; i < 4; i++)
                ldsm_x4(a[i], uA + (uint32_t)(((a_r + i * 16) * KPITCH + kof + a_k) * 2));
            #pragma unroll
            for (int gp = 0; gp < 2; gp++) {
                uint32_t b[2][4];
                #pragma unroll
                for (int g = 0; g < 2; g++)
                    ldsm_x4(b[g], uB + (uint32_t)(((b_r + (gp * 2 + g) * 16) * KPITCH + kof + b_k) * 2));
                #pragma unroll
                for (int i = 0; i < 4; i++)
                    #pragma unroll
                    for (int nn = 0; nn < 4; nn++)
                        mma16816(acc[i][gp * 4 + nn], a[i], &b[nn >> 1][(nn & 1) * 2]);
            }
        }
    }
    __syncthreads();   // all compute done before staging overwrites tiles

    // Stage accumulators to smem, fused epilogue to GMEM.
    const int c_r = lane >> 2;
    const int c_c = (lane & 3) << 1;
    #pragma unroll
    for (int i = 0; i < 4; i++)
        #pragma unroll
        for (int n = 0; n < 8; n++) {
            int r0 = wm * 64 + i * 16 + c_r;
            int c0 = wn * 64 + n * 8 + c_c;
            stg[r0 * SPITCH + c0]           = acc[i][n][0];
            stg[r0 * SPITCH + c0 + 1]       = acc[i][n][1];
            stg[(r0 + 8) * SPITCH + c0]     = acc[i][n][2];
            stg[(r0 + 8) * SPITCH + c0 + 1] = acc[i][n][3];
        }
    __syncthreads();

    const int cc = tid & 31;                  // 32 f4-columns
    const int rg = tid >> 5;                  // 4 row groups of 32
    const int ncol = bx * 128 + cc * 4;
    float4 bb = *(const float4*)&bias[ncol];
    #pragma unroll 4
    for (int rr = 0; rr < 32; rr++) {
        int row = rg * 32 + rr;
        size_t m = arow + row;
        float4 v = *(float4*)&stg[row * SPITCH + cc * 4];
        v.x += bb.x; v.y += bb.y; v.z += bb.z; v.w += bb.w;
        if (GELU_) {
            v.x = gelu_exact(v.x); v.y = gelu_exact(v.y);
            v.z = gelu_exact(v.z); v.w = gelu_exact(v.w);
        }
        if (RES_) {
            float4 rv = *(const float4*)&residual[m * N + ncol];
            v.x += rv.x; v.y += rv.y; v.z += rv.z; v.w += rv.w;
        }
        if (OUTF) *(float4*)&Cf[m * N + ncol] = v;
        if (OUTB) {
            size_t o = m * N + ncol;
            *(__half2*)&Ch[o]     = __floats2half2_rn(v.x, v.y);
            *(__half2*)&Ch[o + 2] = __floats2half2_rn(v.z, v.w);
        }
    }
}

// ----------------------------------------------------------------------------
// Tensor-core flash attention (validated R9, unchanged). 128 threads.
// ----------------------------------------------------------------------------
#define AQP 72
#define ATT_SMEM (5 * 64 * AQP * 2)

__global__ void __launch_bounds__(128) attn_mma_kernel(const __half* __restrict__ QKV,
                                                       __half* __restrict__ O)
{
    extern __shared__ __align__(16) __half smh[];
    __half* Qs = smh;

    int qb = blockIdx.x;
    int bh = blockIdx.y;
    int b = bh >> 4, h = bh & 15;
    int tid = threadIdx.x, w = tid >> 5, lane = tid & 31;

    const size_t rowbase = (size_t)(b * Sn) * 3072 + (size_t)h * 64;

    #pragma unroll
    for (int i = 0; i < 4; i++) {
        int idx = tid + i * 128;
        int row = idx >> 3, c = idx & 7;
        cp_async16(&Qs[row * AQP + c * 8],
                   QKV + rowbase + (size_t)(qb * 64 + row) * 3072 + c * 8);
    }
    CP_COMMIT();

    auto load_kv = [&](int kb, int st) {
        __half* K_s = smh + 64 * AQP * (1 + st);
        __half* V_s = smh + 64 * AQP * (3 + st);
        #pragma unroll
        for (int i = 0; i < 4; i++) {
            int idx = tid + i * 128;
            int row = idx >> 3, c = idx & 7;
            size_t src = rowbase + (size_t)(kb * 64 + row) * 3072 + c * 8;
            cp_async16(&K_s[row * AQP + c * 8], QKV + src + 1024);
            cp_async16(&V_s[row * AQP + c * 8], QKV + src + 2048);
        }
    };
    load_kv(0, 0); CP_COMMIT();
    CP_WAIT(0);
    __syncthreads();

    uint32_t aQ[4][4];
    {
        const uint32_t uQ = smem_u32(Qs);
        int a_r = w * 16 + (lane & 15);
        int a_k = (lane >> 4) << 3;
        #pragma unroll
        for (int t = 0; t < 4; t++)
            ldsm_x4(aQ[t], uQ + (uint32_t)((a_r * AQP + t * 16 + a_k) * 2));
    }

    const int bk_r = ((lane >> 4) << 3) + (lane & 7);
    const int bk_k = ((lane >> 3) & 1) << 3;
    const int bv_r = (((lane >> 3) & 1) << 3) + (lane & 7);
    const int bv_c = (lane >> 4) << 3;

    float o[8][4];
    #pragma unroll
    for (int j = 0; j < 8; j++)
        #pragma unroll
        for (int e = 0; e < 4; e++) o[j][e] = 0.0f;
    float m0 = -1e30f, m1 = -1e30f, l0 = 0.0f, l1 = 0.0f;

    const int qg0 = qb * 64 + w * 16 + (lane >> 2);

    for (int kb = 0; kb <= qb; kb++) {
        const int st = kb & 1;
        if (kb < qb) { load_kv(kb + 1, st ^ 1); CP_COMMIT(); }

        const uint32_t uK = smem_u32(smh + 64 * AQP * (1 + st));
        const uint32_t uV = smem_u32(smh + 64 * AQP * (3 + st));

        float s[8][4];
        #pragma unroll
        for (int j = 0; j < 8; j++)
            #pragma unroll
            for (int e = 0; e < 4; e++) s[j][e] = 0.0f;
        #pragma unroll
        for (int t = 0; t < 4; t++) {
            uint32_t bK[4][4];
            #pragma unroll
            for (int g = 0; g < 4; g++)
                ldsm_x4(bK[g], uK + (uint32_t)(((g * 16 + bk_r) * AQP + t * 16 + bk_k) * 2));
            #pragma unroll
            for (int j = 0; j < 8; j++)
                mma16816(s[j], aQ[t], &bK[j >> 1][(j & 1) * 2]);
        }

        #pragma unroll
        for (int j = 0; j < 8; j++)
            #pragma unroll
            for (int e = 0; e < 4; e++) s[j][e] *= 0.125f;
        if (kb == qb) {
            #pragma unroll
            for (int j = 0; j < 8; j++) {
                int col = kb * 64 + j * 8 + (lane & 3) * 2;
                if (col     > qg0)     s[j][0] = -1e30f;
                if (col + 1 > qg0)     s[j][1] = -1e30f;
                if (col     > qg0 + 8) s[j][2] = -1e30f;
                if (col + 1 > qg0 + 8) s[j][3] = -1e30f;
            }
        }

        float ml0 = -1e30f, ml1 = -1e30f;
        #pragma unroll
        for (int j = 0; j < 8; j++) {
            ml0 = fmaxf(ml0, fmaxf(s[j][0], s[j][1]));
            ml1 = fmaxf(ml1, fmaxf(s[j][2], s[j][3]));
        }
        ml0 = fmaxf(ml0, __shfl_xor_sync(0xffffffffu, ml0, 1));
        ml0 = fmaxf(ml0, __shfl_xor_sync(0xffffffffu, ml0, 2));
        ml1 = fmaxf(ml1, __shfl_xor_sync(0xffffffffu, ml1, 1));
        ml1 = fmaxf(ml1, __shfl_xor_sync(0xffffffffu, ml1, 2));

        float mn0 = fmaxf(m0, ml0), mn1 = fmaxf(m1, ml1);
        float al0 = __expf(m0 - mn0), al1 = __expf(m1 - mn1);

        float ls0 = 0.0f, ls1 = 0.0f;
        uint32_t pfrag[4][4];
        #pragma unroll
        for (int j = 0; j < 8; j++) {
            float p0 = __expf(s[j][0] - mn0);
            float p1 = __expf(s[j][1] - mn0);
            float p2 = __expf(s[j][2] - mn1);
            float p3 = __expf(s[j][3] - mn1);
            ls0 += p0 + p1; ls1 += p2 + p3;
            int t = j >> 1, hi = (j & 1) * 2;
            __half2 h01 = __floats2half2_rn(p0, p1);
            __half2 h23 = __floats2half2_rn(p2, p3);
            pfrag[t][hi]     = *(uint32_t*)&h01;
            pfrag[t][hi + 1] = *(uint32_t*)&h23;
        }
        ls0 += __shfl_xor_sync(0xffffffffu, ls0, 1);
        ls0 += __shfl_xor_sync(0xffffffffu, ls0, 2);
        ls1 += __shfl_xor_sync(0xffffffffu, ls1, 1);
        ls1 += __shfl_xor_sync(0xffffffffu, ls1, 2);

        l0 = l0 * al0 + ls0;  l1 = l1 * al1 + ls1;
        m0 = mn0;             m1 = mn1;
        #pragma unroll
        for (int j = 0; j < 8; j++) {
            o[j][0] *= al0; o[j][1] *= al0;
            o[j][2] *= al1; o[j][3] *= al1;
        }

        #pragma unroll
        for (int t = 0; t < 4; t++) {
            uint32_t bV[4][4];
            #pragma unroll
            for (int g = 0; g < 4; g++)
                ldsm_x4_t(bV[g], uV + (uint32_t)(((t * 16 + bv_r) * AQP + g * 16 + bv_c) * 2));
            #pragma unroll
            for (int j = 0; j < 8; j++)
                mma16816(o[j], pfrag[t], &bV[j >> 1][(j & 1) * 2]);
        }

        if (kb < qb) CP_WAIT(0);
        __syncthreads();
    }

    float inv0 = 1.0f / l0, inv1 = 1.0f / l1;
    size_t ob = (size_t)(b * Sn + qb * 64 + w * 16 + (lane >> 2)) * Dn + h * 64;
    #pragma unroll
    for (int j = 0; j < 8; j++) {
        int col = j * 8 + (lane & 3) * 2;
        __half2 v0 = __floats2half2_rn(o[j][0] * inv0, o[j][1] * inv0);
        __half2 v1 = __floats2half2_rn(o[j][2] * inv1, o[j][3] * inv1);
        *(__half2*)&O[ob + col]           = v0;
        *(__half2*)&O[ob + 8 * Dn + col]  = v1;
    }
}

// ----------------------------------------------------------------------------
// Launch (launch 3 = QKV GEMM for ncu capture)
// ----------------------------------------------------------------------------
extern "C" void kernel_launch(void* const* d_in, const int* in_sizes, int n_in,
                              void* d_out, int out_size)
{
    const float* x     = (const float*)d_in[0];
    const float* Wq    = (const float*)d_in[1];
    const float* Wk    = (const float*)d_in[2];
    const float* Wv    = (const float*)d_in[3];
    const float* bq    = (const float*)d_in[4];
    const float* bk    = (const float*)d_in[5];
    const float* bv    = (const float*)d_in[6];
    const float* Wo    = (const float*)d_in[7];
    const float* bo    = (const float*)d_in[8];
    const float* W1    = (const float*)d_in[9];
    const float* b1    = (const float*)d_in[10];
    const float* W2    = (const float*)d_in[11];
    const float* b2    = (const float*)d_in[12];
    const float* gamma = (const float*)d_in[13];
    const float* beta  = (const float*)d_in[14];
    float* out = (float*)d_out;

    float *bp;
    __half *qkv, *hA, *at, *h1, *wq, *wo, *w1, *w2;
    cudaGetSymbolAddress((void**)&qkv, g_qkv);
    cudaGetSymbolAddress((void**)&bp,  g_bp);
    cudaGetSymbolAddress((void**)&hA,  g_hA);
    cudaGetSymbolAddress((void**)&at,  g_at);
    cudaGetSymbolAddress((void**)&h1,  g_h1);
    cudaGetSymbolAddress((void**)&wq,  g_wqkvT);
    cudaGetSymbolAddress((void**)&wo,  g_woT);
    cudaGetSymbolAddress((void**)&w1,  g_w1T);
    cudaGetSymbolAddress((void**)&w2,  g_w2T);

    cudaFuncSetAttribute(mma_gemm_kernel<false, false, false, true >,
                         cudaFuncAttributeMaxDynamicSharedMemorySize, GEMM_SMEM);
    cudaFuncSetAttribute(mma_gemm_kernel<false, true,  true,  false>,
                         cudaFuncAttributeMaxDynamicSharedMemorySize, GEMM_SMEM);
    cudaFuncSetAttribute(mma_gemm_kernel<true,  false, false, true >,
                         cudaFuncAttributeMaxDynamicSharedMemorySize, GEMM_SMEM);
    cudaFuncSetAttribute(attn_mma_kernel,
                         cudaFuncAttributeMaxDynamicSharedMemorySize, ATT_SMEM);

    dim3 tb(32, 8);
    qkv_pack_kernel<<<dim3(2, 32, 48), tb>>>(Wq, Wk, Wv, wq);
    bias_pack_kernel<<<12, 256>>>(bq, bk, bv, bp);
    ln_kernel<<<Mrows, 256>>>(x, gamma, beta, hA);

    // 3: QKV GEMM -> fp16 qkv   (ncu capture lands here)
    mma_gemm_kernel<false, false, false, true><<<dim3(3 * Dn / 128, Mrows / 128), 128, GEMM_SMEM>>>(
        hA, wq, bp, x, out, qkv, 3 * Dn, Dn);

    // 4: tensor-core attention -> fp16 at
    attn_mma_kernel<<<dim3(Sn / 64, Bn * Hn), 128, ATT_SMEM>>>(qkv, at);

    // Wo pack + GEMM (+x residual) -> fp32 out
    transpose_pack_kernel<<<dim3(32, 32), tb>>>(Wo, wo, Dn, Dn);
    mma_gemm_kernel<false, true, true, false><<<dim3(Dn / 128, Mrows / 128), 128, GEMM_SMEM>>>(
        at, wo, bo, x, out, qkv, Dn, Dn);

    // LN2
    ln_kernel<<<Mrows, 256>>>(out, gamma, beta, hA);

    // W1 pack + MLP1 (+GELU) -> fp16 h1
    transpose_pack_kernel<<<dim3(128, 32), tb>>>(W1, w1, Dn, D4);
    mma_gemm_kernel<true, false, false, true><<<dim3(D4 / 128, Mrows / 128), 128, GEMM_SMEM>>>(
        hA, w1, b1, x, out, h1, D4, Dn);

    // W2 pack + MLP2 (+out residual) -> fp32 out
    transpose_pack_kernel<<<dim3(32, 128), tb>>>(W2, w2, D4, Dn);
    mma_gemm_kernel<false, true, true, false><<<dim3(Dn / 128, Mrows / 128), 128, GEMM_SMEM>>>(
        h1, w2, b2, out, out, qkv, Dn, D4);
}